// round 5
// baseline (speedup 1.0000x reference)
#include <cuda_runtime.h>
#include <cuda_fp16.h>
#include <cuda_bf16.h>
#include <cstdint>

#define B_SZ 4
#define L_SZ 1024
#define DM   1024
#define DI   2048
#define DS   16
#define DTR  64
#define NTOK (B_SZ * L_SZ)   // 4096

// ---------------- scratch ---------------------------------------------------
__device__ float g_xz[NTOK * 2 * DI];        // in_proj output [m][4096]
__device__ float g_xc[NTOK * DI];            // token-major (combine)
__device__ float g_dtT[NTOK * DI];           // [b, d, t]
__device__ float g_xcT[NTOK * DI];           // [b, d, t]
__device__ float g_Bm[NTOK * DS];
__device__ float g_Cm[NTOK * DS];
__device__ float g_yT[NTOK * DI];            // [b, d, t]
__device__ unsigned char g_maskc[NTOK];

// fp16 split-2 activations (hi+lo), fp16 weights
__device__ __half g_nh[NTOK * DM];
__device__ __half g_nl[NTOK * DM];
__device__ __half g_wih[2 * DI * DM];
__device__ __half g_yh[NTOK * DI];
__device__ __half g_yl[NTOK * DI];
__device__ __half g_woh[DM * DI];

// ======================= base-ISA helpers ==================================
__device__ __forceinline__ uint32_t smem_u32(const void* p) {
    uint32_t a;
    asm("{ .reg .u64 t; cvta.to.shared.u64 t, %1; cvt.u32.u64 %0, t; }" : "=r"(a) : "l"(p));
    return a;
}
__device__ __forceinline__ void cp_async16(uint32_t dst, const void* src) {
    asm volatile("cp.async.cg.shared.global [%0], [%1], 16;" :: "r"(dst), "l"(src) : "memory");
}
#define CP_COMMIT() asm volatile("cp.async.commit_group;" ::: "memory")
#define CP_WAIT1()  asm volatile("cp.async.wait_group 1;" ::: "memory")

__device__ __forceinline__ void ldsm4(uint32_t* r, uint32_t a) {
    asm volatile("ldmatrix.sync.aligned.m8n8.x4.shared.b16 {%0,%1,%2,%3}, [%4];"
        : "=r"(r[0]), "=r"(r[1]), "=r"(r[2]), "=r"(r[3]) : "r"(a));
}
__device__ __forceinline__ void mma16816h(float* c, const uint32_t* a, const uint32_t* b) {
    asm volatile("mma.sync.aligned.m16n8k16.row.col.f32.f16.f16.f32 "
        "{%0,%1,%2,%3}, {%4,%5,%6,%7}, {%8,%9}, {%0,%1,%2,%3};"
        : "+f"(c[0]), "+f"(c[1]), "+f"(c[2]), "+f"(c[3])
        : "r"(a[0]), "r"(a[1]), "r"(a[2]), "r"(a[3]), "r"(b[0]), "r"(b[1]));
}

// ---------------- mask canonicalization ------------------------------------
__global__ void mask_prep_kernel(const void* maskraw, int n) {
    __shared__ int isint;
    if (threadIdx.x == 0) {
        const unsigned char* p = (const unsigned char*)maskraw;
        int nz = 0;
        for (int i = 0; i < 32; i++) {
            nz += (p[i * 4 + 1] != 0);
            nz += (p[i * 4 + 2] != 0);
            nz += (p[i * 4 + 3] != 0);
        }
        isint = (nz == 0);
    }
    __syncthreads();
    int ii = isint;
    for (int i = threadIdx.x; i < n; i += blockDim.x) {
        unsigned char v;
        if (ii) v = (((const int*)maskraw)[i] != 0);
        else    v = (((const unsigned char*)maskraw)[i] != 0);
        g_maskc[i] = v;
    }
}

// ---------------- fp32 -> fp16 weight convert -------------------------------
__device__ __forceinline__ void cvt_body(const float* __restrict__ src,
                                         __half* __restrict__ dst, int n4) {
    int i = blockIdx.x * 256 + threadIdx.x;
    if (i < n4) {
        float4 v = ((const float4*)src)[i];
        __half2* hp = (__half2*)(dst + i * 4);
        hp[0] = __floats2half2_rn(v.x, v.y);
        hp[1] = __floats2half2_rn(v.z, v.w);
    }
}
__global__ __launch_bounds__(256) void cvt_win_kernel(const float* __restrict__ s) {
    cvt_body(s, g_wih, (2 * DI * DM) / 4);
}
__global__ __launch_bounds__(256) void cvt_wout_kernel(const float* __restrict__ s) {
    cvt_body(s, g_woh, (DM * DI) / 4);
}

// ---------------- rmsnorm (writes fp16 hi/lo) -------------------------------
__global__ __launch_bounds__(256) void rmsnorm_kernel(const float* __restrict__ x,
                                                      const float* __restrict__ w) {
    int m = blockIdx.x;
    const float* xr = x + (size_t)m * DM;
    float s = 0.f;
    for (int i = threadIdx.x; i < DM; i += 256) { float v = xr[i]; s += v * v; }
    __shared__ float red[8];
    for (int o = 16; o; o >>= 1) s += __shfl_xor_sync(0xffffffffu, s, o);
    if ((threadIdx.x & 31) == 0) red[threadIdx.x >> 5] = s;
    __syncthreads();
    if (threadIdx.x < 8) {
        float v = red[threadIdx.x];
        for (int o = 4; o; o >>= 1) v += __shfl_xor_sync(0xffu, v, o);
        if (threadIdx.x == 0) red[0] = v;
    }
    __syncthreads();
    float scale = rsqrtf(red[0] * (1.0f / DM) + 1e-6f);
    for (int i = threadIdx.x; i < DM; i += 256) {
        float v = xr[i] * scale * w[i];
        __half h = __float2half_rn(v);
        g_nh[(size_t)m * DM + i] = h;
        g_nl[(size_t)m * DM + i] = __float2half_rn(v - __half2float(h));
    }
}

// =================== HMMA fp16 split-2 GEMM =================================
#define G_ROWB   80
#define G_OPB    (128 * G_ROWB)
#define G_STAGEB (3 * G_OPB)
#define G_SMEM   (2 * G_STAGEB)

__device__ __forceinline__ void gemm_hmma(const __half* __restrict__ Ah,
                                          const __half* __restrict__ Al,
                                          const __half* __restrict__ Wh,
                                          float* __restrict__ C, int N, int K,
                                          const float* __restrict__ xres, int epi) {
    extern __shared__ char gsm[];
    uint32_t sbase = smem_u32(gsm);
    const int tid = threadIdx.x;
    const int wid = tid >> 5, lane = tid & 31;
    const int wm = wid & 1, wn = wid >> 1;
    const int bx = blockIdx.x, by = blockIdx.y;

    const __half* srcs[3] = {
        Ah + (size_t)by * 128 * K, Al + (size_t)by * 128 * K,
        Wh + (size_t)bx * 128 * K };

    float acc[4][4][4];
#pragma unroll
    for (int i = 0; i < 4; i++)
#pragma unroll
        for (int j = 0; j < 4; j++)
#pragma unroll
            for (int q = 0; q < 4; q++) acc[i][j][q] = 0.f;

    int lrow[6], lkg[6], lop[6];
#pragma unroll
    for (int p = 0; p < 6; p++) {
        int i = p * 256 + tid;
        lop[p] = i >> 9;
        int w = i & 511;
        lrow[p] = w >> 2;
        lkg[p] = w & 3;
    }

    auto load_stage = [&](int s, int k0) {
        uint32_t sb = sbase + s * G_STAGEB;
#pragma unroll
        for (int p = 0; p < 6; p++) {
            const __half* src = srcs[lop[p]] + (size_t)lrow[p] * K + k0 + lkg[p] * 8;
            cp_async16(sb + lop[p] * G_OPB + lrow[p] * G_ROWB + lkg[p] * 16, src);
        }
        CP_COMMIT();
    };

    const int NC = K >> 5;
    load_stage(0, 0);
    load_stage(1, 32);

    const int a_row = wm * 64 + (lane & 15);
    const int a_cb  = (lane >> 4) * 16;
    const int w_row = wn * 32 + (lane & 7) + ((lane >> 4) & 1) * 8;
    const int w_cb  = ((lane >> 3) & 1) * 16;

    for (int ch = 0; ch < NC; ++ch) {
        CP_WAIT1();
        __syncthreads();
        uint32_t st = sbase + (ch & 1) * G_STAGEB;
        uint32_t ah = st, al = st + G_OPB, wh = st + 2 * G_OPB;
#pragma unroll
        for (int kk = 0; kk < 2; ++kk) {
            int kb = kk * 32;
            uint32_t fAh[4][4], fAl[4][4], fW[4][2];
#pragma unroll
            for (int mt = 0; mt < 4; mt++) {
                uint32_t off = (uint32_t)(a_row + mt * 16) * G_ROWB + a_cb + kb;
                ldsm4(fAh[mt], ah + off);
                ldsm4(fAl[mt], al + off);
            }
#pragma unroll
            for (int p = 0; p < 2; p++) {
                uint32_t off = (uint32_t)(w_row + p * 16) * G_ROWB + w_cb + kb;
                uint32_t r[4];
                ldsm4(r, wh + off);
                fW[p * 2][0] = r[0]; fW[p * 2][1] = r[1];
                fW[p * 2 + 1][0] = r[2]; fW[p * 2 + 1][1] = r[3];
            }
            // all Ah-product MMAs first (16 independent accs), then Al:
            // dependent-acc reuse distance 2 -> 16.
#pragma unroll
            for (int mt = 0; mt < 4; mt++)
#pragma unroll
                for (int nt = 0; nt < 4; nt++)
                    mma16816h(acc[mt][nt], fAh[mt], fW[nt]);
#pragma unroll
            for (int mt = 0; mt < 4; mt++)
#pragma unroll
                for (int nt = 0; nt < 4; nt++)
                    mma16816h(acc[mt][nt], fAl[mt], fW[nt]);
        }
        __syncthreads();
        if (ch + 2 < NC) load_stage(ch & 1, (ch + 2) * 32);
    }

    const int r0 = by * 128 + wm * 64 + (lane >> 2);
    const int c0 = bx * 128 + wn * 32 + (lane & 3) * 2;
#pragma unroll
    for (int mt = 0; mt < 4; mt++) {
        int rowA = r0 + mt * 16, rowB = rowA + 8;
        int mA = epi ? (int)g_maskc[rowA] : 1;
        int mB = epi ? (int)g_maskc[rowB] : 1;
#pragma unroll
        for (int nt = 0; nt < 4; nt++) {
            int col = c0 + nt * 8;
            float2 vA = make_float2(acc[mt][nt][0], acc[mt][nt][1]);
            float2 vB = make_float2(acc[mt][nt][2], acc[mt][nt][3]);
            if (epi) {
                if (mA) {
                    float2 r = *(const float2*)(xres + (size_t)rowA * N + col);
                    vA.x += r.x; vA.y += r.y;
                } else vA = make_float2(0.f, 0.f);
                if (mB) {
                    float2 r = *(const float2*)(xres + (size_t)rowB * N + col);
                    vB.x += r.x; vB.y += r.y;
                } else vB = make_float2(0.f, 0.f);
            }
            *(float2*)(C + (size_t)rowA * N + col) = vA;
            *(float2*)(C + (size_t)rowB * N + col) = vB;
        }
    }
}

__global__ __launch_bounds__(256) void gemm_inproj_kernel() {
    gemm_hmma(g_nh, g_nl, g_wih, g_xz, 2 * DI, DM, nullptr, 0);
}
__global__ __launch_bounds__(256) void gemm_outproj_kernel(const float* __restrict__ x,
                                                           float* __restrict__ out) {
    gemm_hmma(g_yh, g_yl, g_woh, out, DM, DI, x, 1);
}

// ====== fused conv+silu + x_proj + dt_proj (+softplus), 8 tokens/block ======
// writes: g_xc (token-major), g_xcT/g_dtT ([b,d,t], 32B sectors), g_Bm, g_Cm
#define FX_SMEM (8 * 2048 * 4 + 8 * 64 * 4 + 96 * 8 * 4)
__global__ __launch_bounds__(256) void conv_xproj_kernel(const float* __restrict__ convw,
                                                         const float* __restrict__ convb,
                                                         const float* __restrict__ xpw,
                                                         const float* __restrict__ dtw,
                                                         const float* __restrict__ dtb) {
    extern __shared__ float xsm[];
    float* sxc  = xsm;                 // [8][2048]
    float* sdt  = xsm + 8 * 2048;      // [8][64]
    float* sout = sdt + 8 * 64;        // [96][8]
    const int m0 = blockIdx.x * 8;
    const int b  = m0 >> 10;
    const int t0 = m0 & (L_SZ - 1);

    // ---- Phase A: conv + silu ----
    unsigned char mk[11];
#pragma unroll
    for (int r = 0; r < 11; r++) {
        int mrow = m0 - 3 + r;
        mk[r] = (mrow >= 0) ? g_maskc[mrow] : (unsigned char)0;
    }
#pragma unroll
    for (int i = 0; i < 8; i++) {
        int c = i * 256 + threadIdx.x;
        float w0 = convw[c * 4 + 0], w1 = convw[c * 4 + 1];
        float w2 = convw[c * 4 + 2], w3 = convw[c * 4 + 3];
        float cb = convb[c];
        float xr[11];
#pragma unroll
        for (int r = 0; r < 11; r++) {
            int mrow = m0 - 3 + r;
            xr[r] = (mrow >= 0) ? g_xz[(size_t)mrow * (2 * DI) + c] : 0.f;
        }
        float xcv[8];
#pragma unroll
        for (int tt = 0; tt < 8; tt++) {
            int tloc = t0 + tt;
            float acc = cb;
            if (mk[tt + 3]) {
                acc += w3 * xr[tt + 3];
                if (tloc >= 1 && mk[tt + 2]) {
                    acc += w2 * xr[tt + 2];
                    if (tloc >= 2 && mk[tt + 1]) {
                        acc += w1 * xr[tt + 1];
                        if (tloc >= 3 && mk[tt]) acc += w0 * xr[tt];
                    }
                }
            }
            float s = acc / (1.0f + __expf(-acc));
            xcv[tt] = s;
            sxc[tt * 2048 + c] = s;
            g_xc[(size_t)(m0 + tt) * DI + c] = s;   // coalesced across warp
        }
        float4* p = (float4*)&g_xcT[((size_t)b * DI + c) * L_SZ + t0];
        p[0] = make_float4(xcv[0], xcv[1], xcv[2], xcv[3]);
        p[1] = make_float4(xcv[4], xcv[5], xcv[6], xcv[7]);
    }
    __syncthreads();

    // ---- Phase B: x_proj (96 outputs x 8 tokens) ----
    int wid = threadIdx.x >> 5, lid = threadIdx.x & 31;
    for (int e0 = wid * 2; e0 < 96; e0 += 16) {
        const float* wr0 = xpw + (size_t)e0 * DI;
        const float* wr1 = xpw + (size_t)(e0 + 1) * DI;
        float a0[8], a1[8];
#pragma unroll
        for (int t = 0; t < 8; t++) { a0[t] = 0.f; a1[t] = 0.f; }
        for (int k = lid; k < DI; k += 32) {
            float wv0 = wr0[k], wv1 = wr1[k];
#pragma unroll
            for (int t = 0; t < 8; t++) {
                float xv = sxc[t * 2048 + k];
                a0[t] = fmaf(wv0, xv, a0[t]);
                a1[t] = fmaf(wv1, xv, a1[t]);
            }
        }
#pragma unroll
        for (int t = 0; t < 8; t++) {
            for (int o = 16; o; o >>= 1) {
                a0[t] += __shfl_xor_sync(0xffffffffu, a0[t], o);
                a1[t] += __shfl_xor_sync(0xffffffffu, a1[t], o);
            }
        }
        if (lid == 0) {
#pragma unroll
            for (int t = 0; t < 8; t++) { sout[e0 * 8 + t] = a0[t]; sout[(e0 + 1) * 8 + t] = a1[t]; }
        }
    }
    __syncthreads();
    for (int i = threadIdx.x; i < 96 * 8; i += 256) {
        int e = i >> 3, t = i & 7;
        float v = sout[i];
        if (e < DTR)      sdt[t * DTR + e] = v;
        else if (e < 80)  g_Bm[(m0 + t) * DS + (e - DTR)] = v;
        else              g_Cm[(m0 + t) * DS + (e - 80)] = v;
    }
    __syncthreads();

    // ---- Phase C: dt_proj + softplus -> dtT directly ----
    for (int d = threadIdx.x; d < DI; d += 256) {
        const float* wr = dtw + (size_t)d * DTR;
        float bb = dtb[d];
        float a[8];
#pragma unroll
        for (int t = 0; t < 8; t++) a[t] = bb;
#pragma unroll
        for (int r = 0; r < DTR; r++) {
            float wv = wr[r];
#pragma unroll
            for (int t = 0; t < 8; t++) a[t] = fmaf(sdt[t * DTR + r], wv, a[t]);
        }
        float o[8];
#pragma unroll
        for (int t = 0; t < 8; t++) {
            float v = a[t];
            o[t] = (v > 20.f) ? v : log1pf(__expf(v));
        }
        float4* p = (float4*)&g_dtT[((size_t)b * DI + d) * L_SZ + t0];
        p[0] = make_float4(o[0], o[1], o[2], o[3]);
        p[1] = make_float4(o[4], o[5], o[6], o[7]);
    }
}

// ---------------- selective scan --------------------------------------------
__global__ __launch_bounds__(256) void scan_kernel(const float* __restrict__ A_log) {
    int gid = (blockIdx.x * 256 + threadIdx.x) >> 4;
    int s = threadIdx.x & 15;
    int b = gid >> 11;
    int d = gid & (DI - 1);
    float a = -__expf(A_log[d * DS + s]);
    const float* dtp = g_dtT + (size_t)(b * DI + d) * L_SZ;
    const float* xcp = g_xcT + (size_t)(b * DI + d) * L_SZ;
    const float* Bp  = g_Bm + (size_t)b * L_SZ * DS;
    const float* Cp  = g_Cm + (size_t)b * L_SZ * DS;
    const unsigned char* mp = g_maskc + b * L_SZ;
    float* yp = g_yT + (size_t)(b * DI + d) * L_SZ;

    float h = 0.f, ybuf = 0.f;
    for (int t = 0; t < L_SZ; t++) {
        float dt = dtp[t];
        float xc = xcp[t];
        float Bv = Bp[t * DS + s];
        float Cv = Cp[t * DS + s];
        float dA = __expf(dt * a);
        float hn = fmaf(dA, h, dt * Bv * xc);
        h = mp[t] ? hn : 0.f;
        float p = h * Cv;
        p += __shfl_xor_sync(0xffffffffu, p, 8);
        p += __shfl_xor_sync(0xffffffffu, p, 4);
        p += __shfl_xor_sync(0xffffffffu, p, 2);
        p += __shfl_xor_sync(0xffffffffu, p, 1);
        if ((t & 15) == s) ybuf = p;
        if ((t & 15) == 15) yp[(t & ~15) + s] = ybuf;
    }
}

// ---------------- combine: (y + D*x_c)*silu(z) -> fp16 hi/lo ----------------
__global__ void combine_kernel(const float* __restrict__ Dp) {
    __shared__ float sh[32][33];
    int b = blockIdx.z, d0 = blockIdx.x * 32, t0 = blockIdx.y * 32;
    int tx = threadIdx.x, ty = threadIdx.y;
#pragma unroll
    for (int i = 0; i < 4; i++) {
        int d = d0 + ty + i * 8;
        sh[ty + i * 8][tx] = g_yT[((size_t)b * DI + d) * L_SZ + t0 + tx];
    }
    __syncthreads();
#pragma unroll
    for (int i = 0; i < 4; i++) {
        int t = t0 + ty + i * 8;
        size_t m = (size_t)b * L_SZ + t;
        int d = d0 + tx;
        float yv  = sh[tx][ty + i * 8];
        float xcv = g_xc[m * DI + d];
        float zv  = g_xz[m * (2 * DI) + DI + d];
        float yy  = fmaf(Dp[d], xcv, yv);
        float sz  = zv / (1.0f + __expf(-zv));
        float res = yy * sz;
        __half h = __float2half_rn(res);
        g_yh[m * DI + d] = h;
        g_yl[m * DI + d] = __float2half_rn(res - __half2float(h));
    }
}

// ---------------- launch ----------------------------------------------------
extern "C" void kernel_launch(void* const* d_in, const int* in_sizes, int n_in,
                              void* d_out, int out_size) {
    const float* x        = (const float*)d_in[0];
    const void*  maskraw  = d_in[1];
    const float* rms_w    = (const float*)d_in[2];
    const float* in_proj  = (const float*)d_in[3];
    const float* conv_w   = (const float*)d_in[4];
    const float* conv_b   = (const float*)d_in[5];
    const float* x_proj   = (const float*)d_in[6];
    const float* dt_proj  = (const float*)d_in[7];
    const float* dt_b     = (const float*)d_in[8];
    const float* A_log    = (const float*)d_in[9];
    const float* Dvec     = (const float*)d_in[10];
    const float* out_proj = (const float*)d_in[11];
    float* out = (float*)d_out;

    cudaFuncSetAttribute(gemm_inproj_kernel,  cudaFuncAttributeMaxDynamicSharedMemorySize, G_SMEM);
    cudaFuncSetAttribute(gemm_outproj_kernel, cudaFuncAttributeMaxDynamicSharedMemorySize, G_SMEM);
    cudaFuncSetAttribute(conv_xproj_kernel,   cudaFuncAttributeMaxDynamicSharedMemorySize, FX_SMEM);

    mask_prep_kernel<<<1, 256>>>(maskraw, NTOK);
    rmsnorm_kernel<<<NTOK, 256>>>(x, rms_w);
    cvt_win_kernel<<<(2 * DI * DM / 4 + 255) / 256, 256>>>(in_proj);

    dim3 g1((2 * DI) / 128, NTOK / 128);           // profiled slot (#4)
    gemm_inproj_kernel<<<g1, 256, G_SMEM>>>();

    cvt_wout_kernel<<<(DM * DI / 4 + 255) / 256, 256>>>(out_proj);

    conv_xproj_kernel<<<NTOK / 8, 256, FX_SMEM>>>(conv_w, conv_b, x_proj, dt_proj, dt_b);

    scan_kernel<<<(B_SZ * DI * DS) / 256, 256>>>(A_log);

    dim3 tg(DI / 32, L_SZ / 32, B_SZ);
    dim3 tb(32, 8);
    combine_kernel<<<tg, tb>>>(Dvec);

    dim3 g2(DM / 128, NTOK / 128);
    gemm_outproj_kernel<<<g2, 256, G_SMEM>>>(x, out);
}

// round 6
// speedup vs baseline: 1.1513x; 1.1513x over previous
#include <cuda_runtime.h>
#include <cuda_fp16.h>
#include <cstdint>

#define B_SZ 4
#define L_SZ 1024
#define DM   1024
#define DI   2048
#define DS   16
#define DTR  64
#define NTOK (B_SZ * L_SZ)   // 4096

// ---------------- scratch ---------------------------------------------------
__device__ float g_xz[NTOK * 2 * DI];        // in_proj output [m][4096]
__device__ float g_xc[NTOK * DI];            // token-major (combine)
__device__ float g_dtT[NTOK * DI];           // [b, d, t]
__device__ float g_xcT[NTOK * DI];           // [b, d, t]
__device__ float g_Bm[NTOK * DS];
__device__ float g_Cm[NTOK * DS];
__device__ float g_yT[NTOK * DI];            // [b, d, t]
__device__ unsigned char g_maskc[NTOK];

// fp16 operands
__device__ __half g_nh[NTOK * DM];
__device__ __half g_wih[2 * DI * DM];
__device__ __half g_yh[NTOK * DI];
__device__ __half g_woh[DM * DI];

// ======================= base-ISA helpers ==================================
__device__ __forceinline__ uint32_t smem_u32(const void* p) {
    uint32_t a;
    asm("{ .reg .u64 t; cvta.to.shared.u64 t, %1; cvt.u32.u64 %0, t; }" : "=r"(a) : "l"(p));
    return a;
}
__device__ __forceinline__ void cp_async16(uint32_t dst, const void* src) {
    asm volatile("cp.async.cg.shared.global [%0], [%1], 16;" :: "r"(dst), "l"(src) : "memory");
}
#define CP_COMMIT() asm volatile("cp.async.commit_group;" ::: "memory")
#define CP_WAIT2()  asm volatile("cp.async.wait_group 2;" ::: "memory")

__device__ __forceinline__ void ldsm4(uint32_t* r, uint32_t a) {
    asm volatile("ldmatrix.sync.aligned.m8n8.x4.shared.b16 {%0,%1,%2,%3}, [%4];"
        : "=r"(r[0]), "=r"(r[1]), "=r"(r[2]), "=r"(r[3]) : "r"(a));
}
__device__ __forceinline__ void mma16816h(float* c, const uint32_t* a, const uint32_t* b) {
    asm volatile("mma.sync.aligned.m16n8k16.row.col.f32.f16.f16.f32 "
        "{%0,%1,%2,%3}, {%4,%5,%6,%7}, {%8,%9}, {%0,%1,%2,%3};"
        : "+f"(c[0]), "+f"(c[1]), "+f"(c[2]), "+f"(c[3])
        : "r"(a[0]), "r"(a[1]), "r"(a[2]), "r"(a[3]), "r"(b[0]), "r"(b[1]));
}

// ---------------- fp32 -> fp16 weight convert -------------------------------
__device__ __forceinline__ void cvt_body(const float* __restrict__ src,
                                         __half* __restrict__ dst, int n4) {
    int i = blockIdx.x * 256 + threadIdx.x;
    if (i < n4) {
        float4 v = ((const float4*)src)[i];
        __half2* hp = (__half2*)(dst + i * 4);
        hp[0] = __floats2half2_rn(v.x, v.y);
        hp[1] = __floats2half2_rn(v.z, v.w);
    }
}
__global__ __launch_bounds__(256) void cvt_win_kernel(const float* __restrict__ s) {
    cvt_body(s, g_wih, (2 * DI * DM) / 4);
}
__global__ __launch_bounds__(256) void cvt_wout_kernel(const float* __restrict__ s) {
    cvt_body(s, g_woh, (DM * DI) / 4);
}

// ---------------- rmsnorm (+ mask canonicalization in block 0) --------------
__global__ __launch_bounds__(256) void rmsnorm_kernel(const float* __restrict__ x,
                                                      const float* __restrict__ w,
                                                      const void* maskraw) {
    int m = blockIdx.x;
    if (m == 0) {
        // mask: detect int32 vs byte-bool storage (high bytes all zero -> int)
        const unsigned char* p = (const unsigned char*)maskraw;
        int nz = 0;
        for (int i = 0; i < 32; i++)
            nz += (p[i * 4 + 1] != 0) + (p[i * 4 + 2] != 0) + (p[i * 4 + 3] != 0);
        int isint = (nz == 0);
        for (int i = threadIdx.x; i < NTOK; i += 256) {
            unsigned char v;
            if (isint) v = (((const int*)maskraw)[i] != 0);
            else       v = (((const unsigned char*)maskraw)[i] != 0);
            g_maskc[i] = v;
        }
    }
    const float* xr = x + (size_t)m * DM;
    float s = 0.f;
    for (int i = threadIdx.x; i < DM; i += 256) { float v = xr[i]; s += v * v; }
    __shared__ float red[8];
    for (int o = 16; o; o >>= 1) s += __shfl_xor_sync(0xffffffffu, s, o);
    if ((threadIdx.x & 31) == 0) red[threadIdx.x >> 5] = s;
    __syncthreads();
    if (threadIdx.x < 8) {
        float v = red[threadIdx.x];
        for (int o = 4; o; o >>= 1) v += __shfl_xor_sync(0xffu, v, o);
        if (threadIdx.x == 0) red[0] = v;
    }
    __syncthreads();
    float scale = rsqrtf(red[0] * (1.0f / DM) + 1e-6f);
    for (int i = threadIdx.x; i < DM; i += 256)
        g_nh[(size_t)m * DM + i] = __float2half_rn(xr[i] * scale * w[i]);
}

// =================== HMMA fp16 GEMM (single product, 3 stages) ==============
#define G_ROWB   80
#define G_OPB    (128 * G_ROWB)          // 10240
#define G_STAGEB (2 * G_OPB)             // 20480
#define G_SMEM   (3 * G_STAGEB)          // 61440

__device__ __forceinline__ void gemm_hmma(const __half* __restrict__ A,
                                          const __half* __restrict__ W,
                                          float* __restrict__ C, int N, int K,
                                          const float* __restrict__ xres, int epi) {
    extern __shared__ char gsm[];
    uint32_t sbase = smem_u32(gsm);
    const int tid = threadIdx.x;
    const int wid = tid >> 5, lane = tid & 31;
    const int wm = wid & 1, wn = wid >> 1;
    const int bx = blockIdx.x, by = blockIdx.y;

    const __half* srcs[2] = { A + (size_t)by * 128 * K, W + (size_t)bx * 128 * K };

    float acc[4][4][4];
#pragma unroll
    for (int i = 0; i < 4; i++)
#pragma unroll
        for (int j = 0; j < 4; j++)
#pragma unroll
            for (int q = 0; q < 4; q++) acc[i][j][q] = 0.f;

    int lrow[4], lkg[4], lop[4];
#pragma unroll
    for (int p = 0; p < 4; p++) {
        int i = p * 256 + tid;      // 0..1023 (2 ops x 512 float4)
        lop[p] = i >> 9;
        int w = i & 511;
        lrow[p] = w >> 2;
        lkg[p] = w & 3;
    }

    auto load_stage = [&](int s, int k0) {
        uint32_t sb = sbase + s * G_STAGEB;
#pragma unroll
        for (int p = 0; p < 4; p++) {
            const __half* src = srcs[lop[p]] + (size_t)lrow[p] * K + k0 + lkg[p] * 8;
            cp_async16(sb + lop[p] * G_OPB + lrow[p] * G_ROWB + lkg[p] * 16, src);
        }
        CP_COMMIT();
    };

    const int NC = K >> 5;
    load_stage(0, 0);
    load_stage(1, 32);
    load_stage(2, 64);

    const int a_row = wm * 64 + (lane & 15);
    const int a_cb  = (lane >> 4) * 16;
    const int w_row = wn * 32 + (lane & 7) + ((lane >> 4) & 1) * 8;
    const int w_cb  = ((lane >> 3) & 1) * 16;

    int sidx = 0;
    for (int ch = 0; ch < NC; ++ch) {
        CP_WAIT2();
        __syncthreads();
        uint32_t st = sbase + sidx * G_STAGEB;
        uint32_t ah = st, wh = st + G_OPB;
#pragma unroll
        for (int kk = 0; kk < 2; ++kk) {
            int kb = kk * 32;
            uint32_t fA[4][4], fW[4][2];
#pragma unroll
            for (int mt = 0; mt < 4; mt++) {
                uint32_t off = (uint32_t)(a_row + mt * 16) * G_ROWB + a_cb + kb;
                ldsm4(fA[mt], ah + off);
            }
#pragma unroll
            for (int p = 0; p < 2; p++) {
                uint32_t off = (uint32_t)(w_row + p * 16) * G_ROWB + w_cb + kb;
                uint32_t r[4];
                ldsm4(r, wh + off);
                fW[p * 2][0] = r[0]; fW[p * 2][1] = r[1];
                fW[p * 2 + 1][0] = r[2]; fW[p * 2 + 1][1] = r[3];
            }
#pragma unroll
            for (int mt = 0; mt < 4; mt++)
#pragma unroll
                for (int nt = 0; nt < 4; nt++)
                    mma16816h(acc[mt][nt], fA[mt], fW[nt]);
        }
        __syncthreads();
        if (ch + 3 < NC) load_stage(sidx, (ch + 3) * 32);
        sidx = (sidx == 2) ? 0 : sidx + 1;
    }

    const int r0 = by * 128 + wm * 64 + (lane >> 2);
    const int c0 = bx * 128 + wn * 32 + (lane & 3) * 2;
#pragma unroll
    for (int mt = 0; mt < 4; mt++) {
        int rowA = r0 + mt * 16, rowB = rowA + 8;
        int mA = epi ? (int)g_maskc[rowA] : 1;
        int mB = epi ? (int)g_maskc[rowB] : 1;
#pragma unroll
        for (int nt = 0; nt < 4; nt++) {
            int col = c0 + nt * 8;
            float2 vA = make_float2(acc[mt][nt][0], acc[mt][nt][1]);
            float2 vB = make_float2(acc[mt][nt][2], acc[mt][nt][3]);
            if (epi) {
                if (mA) {
                    float2 r = *(const float2*)(xres + (size_t)rowA * N + col);
                    vA.x += r.x; vA.y += r.y;
                } else vA = make_float2(0.f, 0.f);
                if (mB) {
                    float2 r = *(const float2*)(xres + (size_t)rowB * N + col);
                    vB.x += r.x; vB.y += r.y;
                } else vB = make_float2(0.f, 0.f);
            }
            *(float2*)(C + (size_t)rowA * N + col) = vA;
            *(float2*)(C + (size_t)rowB * N + col) = vB;
        }
    }
}

__global__ __launch_bounds__(256) void gemm_inproj_kernel() {
    gemm_hmma(g_nh, g_wih, g_xz, 2 * DI, DM, nullptr, 0);
}
__global__ __launch_bounds__(256) void gemm_outproj_kernel(const float* __restrict__ x,
                                                           float* __restrict__ out) {
    gemm_hmma(g_yh, g_woh, out, DM, DI, x, 1);
}

// ====== fused conv+silu + x_proj + dt_proj (+softplus), 8 tokens/block ======
#define FX_SMEM (8 * 2048 * 4 + 8 * 64 * 4 + 96 * 8 * 4)
__global__ __launch_bounds__(256) void conv_xproj_kernel(const float* __restrict__ convw,
                                                         const float* __restrict__ convb,
                                                         const float* __restrict__ xpw,
                                                         const float* __restrict__ dtw,
                                                         const float* __restrict__ dtb) {
    extern __shared__ float xsm[];
    float* sxc  = xsm;                 // [8][2048]
    float* sdt  = xsm + 8 * 2048;      // [8][64]
    float* sout = sdt + 8 * 64;        // [96][8]
    const int m0 = blockIdx.x * 8;
    const int b  = m0 >> 10;
    const int t0 = m0 & (L_SZ - 1);

    unsigned char mk[11];
#pragma unroll
    for (int r = 0; r < 11; r++) {
        int mrow = m0 - 3 + r;
        mk[r] = (mrow >= 0) ? g_maskc[mrow] : (unsigned char)0;
    }
#pragma unroll
    for (int i = 0; i < 8; i++) {
        int c = i * 256 + threadIdx.x;
        float w0 = convw[c * 4 + 0], w1 = convw[c * 4 + 1];
        float w2 = convw[c * 4 + 2], w3 = convw[c * 4 + 3];
        float cb = convb[c];
        float xr[11];
#pragma unroll
        for (int r = 0; r < 11; r++) {
            int mrow = m0 - 3 + r;
            xr[r] = (mrow >= 0) ? g_xz[(size_t)mrow * (2 * DI) + c] : 0.f;
        }
        float xcv[8];
#pragma unroll
        for (int tt = 0; tt < 8; tt++) {
            int tloc = t0 + tt;
            float acc = cb;
            if (mk[tt + 3]) {
                acc += w3 * xr[tt + 3];
                if (tloc >= 1 && mk[tt + 2]) {
                    acc += w2 * xr[tt + 2];
                    if (tloc >= 2 && mk[tt + 1]) {
                        acc += w1 * xr[tt + 1];
                        if (tloc >= 3 && mk[tt]) acc += w0 * xr[tt];
                    }
                }
            }
            float s = acc / (1.0f + __expf(-acc));
            xcv[tt] = s;
            sxc[tt * 2048 + c] = s;
            g_xc[(size_t)(m0 + tt) * DI + c] = s;
        }
        float4* p = (float4*)&g_xcT[((size_t)b * DI + c) * L_SZ + t0];
        p[0] = make_float4(xcv[0], xcv[1], xcv[2], xcv[3]);
        p[1] = make_float4(xcv[4], xcv[5], xcv[6], xcv[7]);
    }
    __syncthreads();

    int wid = threadIdx.x >> 5, lid = threadIdx.x & 31;
    for (int e0 = wid * 2; e0 < 96; e0 += 16) {
        const float* wr0 = xpw + (size_t)e0 * DI;
        const float* wr1 = xpw + (size_t)(e0 + 1) * DI;
        float a0[8], a1[8];
#pragma unroll
        for (int t = 0; t < 8; t++) { a0[t] = 0.f; a1[t] = 0.f; }
        for (int k = lid; k < DI; k += 32) {
            float wv0 = wr0[k], wv1 = wr1[k];
#pragma unroll
            for (int t = 0; t < 8; t++) {
                float xv = sxc[t * 2048 + k];
                a0[t] = fmaf(wv0, xv, a0[t]);
                a1[t] = fmaf(wv1, xv, a1[t]);
            }
        }
#pragma unroll
        for (int t = 0; t < 8; t++) {
            for (int o = 16; o; o >>= 1) {
                a0[t] += __shfl_xor_sync(0xffffffffu, a0[t], o);
                a1[t] += __shfl_xor_sync(0xffffffffu, a1[t], o);
            }
        }
        if (lid == 0) {
#pragma unroll
            for (int t = 0; t < 8; t++) { sout[e0 * 8 + t] = a0[t]; sout[(e0 + 1) * 8 + t] = a1[t]; }
        }
    }
    __syncthreads();
    for (int i = threadIdx.x; i < 96 * 8; i += 256) {
        int e = i >> 3, t = i & 7;
        float v = sout[i];
        if (e < DTR)      sdt[t * DTR + e] = v;
        else if (e < 80)  g_Bm[(m0 + t) * DS + (e - DTR)] = v;
        else              g_Cm[(m0 + t) * DS + (e - 80)] = v;
    }
    __syncthreads();

    for (int d = threadIdx.x; d < DI; d += 256) {
        const float* wr = dtw + (size_t)d * DTR;
        float bb = dtb[d];
        float a[8];
#pragma unroll
        for (int t = 0; t < 8; t++) a[t] = bb;
#pragma unroll
        for (int r = 0; r < DTR; r++) {
            float wv = wr[r];
#pragma unroll
            for (int t = 0; t < 8; t++) a[t] = fmaf(sdt[t * DTR + r], wv, a[t]);
        }
        float o[8];
#pragma unroll
        for (int t = 0; t < 8; t++) {
            float v = a[t];
            o[t] = (v > 20.f) ? v : log1pf(__expf(v));
        }
        float4* p = (float4*)&g_dtT[((size_t)b * DI + d) * L_SZ + t0];
        p[0] = make_float4(o[0], o[1], o[2], o[3]);
        p[1] = make_float4(o[4], o[5], o[6], o[7]);
    }
}

// ---------------- selective scan --------------------------------------------
__global__ __launch_bounds__(256) void scan_kernel(const float* __restrict__ A_log) {
    int gid = (blockIdx.x * 256 + threadIdx.x) >> 4;
    int s = threadIdx.x & 15;
    int b = gid >> 11;
    int d = gid & (DI - 1);
    float a = -__expf(A_log[d * DS + s]);
    const float* dtp = g_dtT + (size_t)(b * DI + d) * L_SZ;
    const float* xcp = g_xcT + (size_t)(b * DI + d) * L_SZ;
    const float* Bp  = g_Bm + (size_t)b * L_SZ * DS;
    const float* Cp  = g_Cm + (size_t)b * L_SZ * DS;
    const unsigned char* mp = g_maskc + b * L_SZ;
    float* yp = g_yT + (size_t)(b * DI + d) * L_SZ;

    float h = 0.f, ybuf = 0.f;
    for (int t4 = 0; t4 < L_SZ; t4 += 4) {
        float4 dt4 = *(const float4*)(dtp + t4);
        float4 xc4 = *(const float4*)(xcp + t4);
        float dts[4] = {dt4.x, dt4.y, dt4.z, dt4.w};
        float xcs[4] = {xc4.x, xc4.y, xc4.z, xc4.w};
#pragma unroll
        for (int q = 0; q < 4; q++) {
            int t = t4 + q;
            float Bv = Bp[t * DS + s];
            float Cv = Cp[t * DS + s];
            float dA = __expf(dts[q] * a);
            float hn = fmaf(dA, h, dts[q] * Bv * xcs[q]);
            h = mp[t] ? hn : 0.f;
            float p = h * Cv;
            p += __shfl_xor_sync(0xffffffffu, p, 8);
            p += __shfl_xor_sync(0xffffffffu, p, 4);
            p += __shfl_xor_sync(0xffffffffu, p, 2);
            p += __shfl_xor_sync(0xffffffffu, p, 1);
            if ((t & 15) == s) ybuf = p;
            if ((t & 15) == 15) yp[(t & ~15) + s] = ybuf;
        }
    }
}

// ---------------- combine: (y + D*x_c)*silu(z) -> fp16 ----------------------
__global__ void combine_kernel(const float* __restrict__ Dp) {
    __shared__ float sh[32][33];
    int b = blockIdx.z, d0 = blockIdx.x * 32, t0 = blockIdx.y * 32;
    int tx = threadIdx.x, ty = threadIdx.y;
#pragma unroll
    for (int i = 0; i < 4; i++) {
        int d = d0 + ty + i * 8;
        sh[ty + i * 8][tx] = g_yT[((size_t)b * DI + d) * L_SZ + t0 + tx];
    }
    __syncthreads();
#pragma unroll
    for (int i = 0; i < 4; i++) {
        int t = t0 + ty + i * 8;
        size_t m = (size_t)b * L_SZ + t;
        int d = d0 + tx;
        float yv  = sh[tx][ty + i * 8];
        float xcv = g_xc[m * DI + d];
        float zv  = g_xz[m * (2 * DI) + DI + d];
        float yy  = fmaf(Dp[d], xcv, yv);
        float sz  = zv / (1.0f + __expf(-zv));
        g_yh[m * DI + d] = __float2half_rn(yy * sz);
    }
}

// ---------------- launch ----------------------------------------------------
extern "C" void kernel_launch(void* const* d_in, const int* in_sizes, int n_in,
                              void* d_out, int out_size) {
    const float* x        = (const float*)d_in[0];
    const void*  maskraw  = d_in[1];
    const float* rms_w    = (const float*)d_in[2];
    const float* in_proj  = (const float*)d_in[3];
    const float* conv_w   = (const float*)d_in[4];
    const float* conv_b   = (const float*)d_in[5];
    const float* x_proj   = (const float*)d_in[6];
    const float* dt_proj  = (const float*)d_in[7];
    const float* dt_b     = (const float*)d_in[8];
    const float* A_log    = (const float*)d_in[9];
    const float* Dvec     = (const float*)d_in[10];
    const float* out_proj = (const float*)d_in[11];
    float* out = (float*)d_out;

    cudaFuncSetAttribute(gemm_inproj_kernel,  cudaFuncAttributeMaxDynamicSharedMemorySize, G_SMEM);
    cudaFuncSetAttribute(gemm_outproj_kernel, cudaFuncAttributeMaxDynamicSharedMemorySize, G_SMEM);
    cudaFuncSetAttribute(conv_xproj_kernel,   cudaFuncAttributeMaxDynamicSharedMemorySize, FX_SMEM);

    // 1: rmsnorm (+mask), 2: cvt_win, 3: gemm_in, 4: conv_xproj (profiled slot)
    rmsnorm_kernel<<<NTOK, 256>>>(x, rms_w, maskraw);
    cvt_win_kernel<<<(2 * DI * DM / 4 + 255) / 256, 256>>>(in_proj);

    dim3 g1((2 * DI) / 128, NTOK / 128);
    gemm_inproj_kernel<<<g1, 256, G_SMEM>>>();

    conv_xproj_kernel<<<NTOK / 8, 256, FX_SMEM>>>(conv_w, conv_b, x_proj, dt_proj, dt_b);

    cvt_wout_kernel<<<(DM * DI / 4 + 255) / 256, 256>>>(out_proj);

    scan_kernel<<<(B_SZ * DI * DS) / 256, 256>>>(A_log);

    dim3 tg(DI / 32, L_SZ / 32, B_SZ);
    dim3 tb(32, 8);
    combine_kernel<<<tg, tb>>>(Dvec);

    dim3 g2(DM / 128, NTOK / 128);
    gemm_outproj_kernel<<<g2, 256, G_SMEM>>>(x, out);
}

// round 7
// speedup vs baseline: 2.0719x; 1.7997x over previous
#include <cuda_runtime.h>
#include <cuda_fp16.h>
#include <cstdint>

#define B_SZ 4
#define L_SZ 1024
#define DM   1024
#define DI   2048
#define DS   16
#define DTR  64
#define NTOK (B_SZ * L_SZ)   // 4096

// ---------------- scratch ---------------------------------------------------
__device__ float g_xz[NTOK * 2 * DI];        // in_proj output [m][4096]
__device__ float g_xc[NTOK * DI];            // token-major fp32 (combine)
__device__ float g_dtT[NTOK * DI];           // [b, d, t]
__device__ float g_xcT[NTOK * DI];           // [b, d, t]
__device__ float g_Bm[NTOK * DS];
__device__ float g_Cm[NTOK * DS];
__device__ float g_yT[NTOK * DI];            // [b, d, t]
__device__ unsigned char g_maskc[NTOK];

// fp16 operands
__device__ __half g_nh[NTOK * DM];
__device__ __half g_wih[2 * DI * DM];
__device__ __half g_yh[NTOK * DI];
__device__ __half g_woh[DM * DI];
__device__ __half g_xch[NTOK * DI];          // conv output fp16 (xproj A)
__device__ __half g_dtr_h[NTOK * DTR];       // dt_r fp16 (dtproj A)
__device__ __half g_xpwh[128 * DI];          // x_proj_w padded to 128 rows
__device__ __half g_dtwh[DI * DTR];          // dt_proj_w fp16

// ======================= base-ISA helpers ==================================
__device__ __forceinline__ uint32_t smem_u32(const void* p) {
    uint32_t a;
    asm("{ .reg .u64 t; cvta.to.shared.u64 t, %1; cvt.u32.u64 %0, t; }" : "=r"(a) : "l"(p));
    return a;
}
__device__ __forceinline__ void cp_async16(uint32_t dst, const void* src) {
    asm volatile("cp.async.cg.shared.global [%0], [%1], 16;" :: "r"(dst), "l"(src) : "memory");
}
#define CP_COMMIT() asm volatile("cp.async.commit_group;" ::: "memory")
#define CP_WAIT2()  asm volatile("cp.async.wait_group 2;" ::: "memory")

__device__ __forceinline__ void ldsm4(uint32_t* r, uint32_t a) {
    asm volatile("ldmatrix.sync.aligned.m8n8.x4.shared.b16 {%0,%1,%2,%3}, [%4];"
        : "=r"(r[0]), "=r"(r[1]), "=r"(r[2]), "=r"(r[3]) : "r"(a));
}
__device__ __forceinline__ void mma16816h(float* c, const uint32_t* a, const uint32_t* b) {
    asm volatile("mma.sync.aligned.m16n8k16.row.col.f32.f16.f16.f32 "
        "{%0,%1,%2,%3}, {%4,%5,%6,%7}, {%8,%9}, {%0,%1,%2,%3};"
        : "+f"(c[0]), "+f"(c[1]), "+f"(c[2]), "+f"(c[3])
        : "r"(a[0]), "r"(a[1]), "r"(a[2]), "r"(a[3]), "r"(b[0]), "r"(b[1]));
}

// ---------------- fp32 -> fp16 weight converts ------------------------------
__device__ __forceinline__ void cvt_body(const float* __restrict__ src,
                                         __half* __restrict__ dst, int n4) {
    int i = blockIdx.x * 256 + threadIdx.x;
    if (i < n4) {
        float4 v = ((const float4*)src)[i];
        __half2* hp = (__half2*)(dst + i * 4);
        hp[0] = __floats2half2_rn(v.x, v.y);
        hp[1] = __floats2half2_rn(v.z, v.w);
    }
}
__global__ __launch_bounds__(256) void cvt_win_kernel(const float* __restrict__ s) {
    cvt_body(s, g_wih, (2 * DI * DM) / 4);
}
__global__ __launch_bounds__(256) void cvt_wout_kernel(const float* __restrict__ s) {
    cvt_body(s, g_woh, (DM * DI) / 4);
}
// xpw (96 rows -> 128 padded) + dtw
__global__ __launch_bounds__(256) void cvt_small_kernel(const float* __restrict__ xpw,
                                                        const float* __restrict__ dtw) {
    int i = blockIdx.x * 256 + threadIdx.x;
    const int nxp4 = (128 * DI) / 4;
    if (i < nxp4) {
        int idx = i * 4;
        int row = idx >> 11;
        __half2 h0, h1;
        if (row < 96) {
            float4 v = ((const float4*)xpw)[i];
            h0 = __floats2half2_rn(v.x, v.y);
            h1 = __floats2half2_rn(v.z, v.w);
        } else {
            h0 = __floats2half2_rn(0.f, 0.f);
            h1 = h0;
        }
        ((__half2*)&g_xpwh[idx])[0] = h0;
        ((__half2*)&g_xpwh[idx])[1] = h1;
    } else {
        int j = i - nxp4;
        if (j < (DI * DTR) / 4) {
            float4 v = ((const float4*)dtw)[j];
            ((__half2*)&g_dtwh[j * 4])[0] = __floats2half2_rn(v.x, v.y);
            ((__half2*)&g_dtwh[j * 4])[1] = __floats2half2_rn(v.z, v.w);
        }
    }
}

// ---------------- rmsnorm (+ mask canonicalization in block 0) --------------
__global__ __launch_bounds__(256) void rmsnorm_kernel(const float* __restrict__ x,
                                                      const float* __restrict__ w,
                                                      const void* maskraw) {
    int m = blockIdx.x;
    if (m == 0) {
        const unsigned char* p = (const unsigned char*)maskraw;
        int nz = 0;
        for (int i = 0; i < 32; i++)
            nz += (p[i * 4 + 1] != 0) + (p[i * 4 + 2] != 0) + (p[i * 4 + 3] != 0);
        int isint = (nz == 0);
        for (int i = threadIdx.x; i < NTOK; i += 256) {
            unsigned char v;
            if (isint) v = (((const int*)maskraw)[i] != 0);
            else       v = (((const unsigned char*)maskraw)[i] != 0);
            g_maskc[i] = v;
        }
    }
    const float* xr = x + (size_t)m * DM;
    float s = 0.f;
    for (int i = threadIdx.x; i < DM; i += 256) { float v = xr[i]; s += v * v; }
    __shared__ float red[8];
    for (int o = 16; o; o >>= 1) s += __shfl_xor_sync(0xffffffffu, s, o);
    if ((threadIdx.x & 31) == 0) red[threadIdx.x >> 5] = s;
    __syncthreads();
    if (threadIdx.x < 8) {
        float v = red[threadIdx.x];
        for (int o = 4; o; o >>= 1) v += __shfl_xor_sync(0xffu, v, o);
        if (threadIdx.x == 0) red[0] = v;
    }
    __syncthreads();
    float scale = rsqrtf(red[0] * (1.0f / DM) + 1e-6f);
    for (int i = threadIdx.x; i < DM; i += 256)
        g_nh[(size_t)m * DM + i] = __float2half_rn(xr[i] * scale * w[i]);
}

// =================== HMMA fp16 GEMM core (3-stage cp.async) =================
// EPI 0: C store. EPI 1: residual+mask. EPI 2: xproj scatter (dtr/B/C).
// EPI 3: dt bias+softplus+transpose -> g_dtT.
#define G_ROWB   80
#define G_OPB    (128 * G_ROWB)          // 10240
#define G_STAGEB (2 * G_OPB)             // 20480
#define G_SMEM   (3 * G_STAGEB)          // 61440

template <int EPI>
__device__ __forceinline__ void gemm_core(const __half* __restrict__ A,
                                          const __half* __restrict__ W,
                                          float* __restrict__ C, int N, int K,
                                          const float* __restrict__ xres,
                                          const float* __restrict__ bias) {
    extern __shared__ char gsm[];
    uint32_t sbase = smem_u32(gsm);
    const int tid = threadIdx.x;
    const int wid = tid >> 5, lane = tid & 31;
    const int wm = wid & 1, wn = wid >> 1;
    const int bx = blockIdx.x, by = blockIdx.y;

    const __half* srcs[2] = { A + (size_t)by * 128 * K, W + (size_t)bx * 128 * K };

    float acc[4][4][4];
#pragma unroll
    for (int i = 0; i < 4; i++)
#pragma unroll
        for (int j = 0; j < 4; j++)
#pragma unroll
            for (int q = 0; q < 4; q++) acc[i][j][q] = 0.f;

    int lrow[4], lkg[4], lop[4];
#pragma unroll
    for (int p = 0; p < 4; p++) {
        int i = p * 256 + tid;
        lop[p] = i >> 9;
        int w = i & 511;
        lrow[p] = w >> 2;
        lkg[p] = w & 3;
    }

    auto load_stage = [&](int s, int k0) {
        if (k0 < K) {
            uint32_t sb = sbase + s * G_STAGEB;
#pragma unroll
            for (int p = 0; p < 4; p++) {
                const __half* src = srcs[lop[p]] + (size_t)lrow[p] * K + k0 + lkg[p] * 8;
                cp_async16(sb + lop[p] * G_OPB + lrow[p] * G_ROWB + lkg[p] * 16, src);
            }
        }
        CP_COMMIT();
    };

    const int NC = K >> 5;
    load_stage(0, 0);
    load_stage(1, 32);
    load_stage(2, 64);

    const int a_row = wm * 64 + (lane & 15);
    const int a_cb  = (lane >> 4) * 16;
    const int w_row = wn * 32 + (lane & 7) + ((lane >> 4) & 1) * 8;
    const int w_cb  = ((lane >> 3) & 1) * 16;

    int sidx = 0;
    for (int ch = 0; ch < NC; ++ch) {
        CP_WAIT2();
        __syncthreads();
        uint32_t st = sbase + sidx * G_STAGEB;
        uint32_t ah = st, wh = st + G_OPB;
#pragma unroll
        for (int kk = 0; kk < 2; ++kk) {
            int kb = kk * 32;
            uint32_t fA[4][4], fW[4][2];
#pragma unroll
            for (int mt = 0; mt < 4; mt++) {
                uint32_t off = (uint32_t)(a_row + mt * 16) * G_ROWB + a_cb + kb;
                ldsm4(fA[mt], ah + off);
            }
#pragma unroll
            for (int p = 0; p < 2; p++) {
                uint32_t off = (uint32_t)(w_row + p * 16) * G_ROWB + w_cb + kb;
                uint32_t r[4];
                ldsm4(r, wh + off);
                fW[p * 2][0] = r[0]; fW[p * 2][1] = r[1];
                fW[p * 2 + 1][0] = r[2]; fW[p * 2 + 1][1] = r[3];
            }
#pragma unroll
            for (int mt = 0; mt < 4; mt++)
#pragma unroll
                for (int nt = 0; nt < 4; nt++)
                    mma16816h(acc[mt][nt], fA[mt], fW[nt]);
        }
        __syncthreads();
        if (ch + 3 < NC) load_stage(sidx, (ch + 3) * 32);
        else CP_COMMIT();                    // keep wait_group accounting exact
        sidx = (sidx == 2) ? 0 : sidx + 1;
    }

    if (EPI == 0 || EPI == 1) {
        const int r0 = by * 128 + wm * 64 + (lane >> 2);
        const int c0 = bx * 128 + wn * 32 + (lane & 3) * 2;
#pragma unroll
        for (int mt = 0; mt < 4; mt++) {
            int rowA = r0 + mt * 16, rowB = rowA + 8;
            int mA = (EPI == 1) ? (int)g_maskc[rowA] : 1;
            int mB = (EPI == 1) ? (int)g_maskc[rowB] : 1;
#pragma unroll
            for (int nt = 0; nt < 4; nt++) {
                int col = c0 + nt * 8;
                float2 vA = make_float2(acc[mt][nt][0], acc[mt][nt][1]);
                float2 vB = make_float2(acc[mt][nt][2], acc[mt][nt][3]);
                if (EPI == 1) {
                    if (mA) {
                        float2 r = *(const float2*)(xres + (size_t)rowA * N + col);
                        vA.x += r.x; vA.y += r.y;
                    } else vA = make_float2(0.f, 0.f);
                    if (mB) {
                        float2 r = *(const float2*)(xres + (size_t)rowB * N + col);
                        vB.x += r.x; vB.y += r.y;
                    } else vB = make_float2(0.f, 0.f);
                }
                *(float2*)(C + (size_t)rowA * N + col) = vA;
                *(float2*)(C + (size_t)rowB * N + col) = vB;
            }
        }
    } else if (EPI == 2) {
        // xproj: cols [0,64) -> dt_r fp16; [64,80) -> Bm; [80,96) -> Cm
        const int r0 = by * 128 + wm * 64 + (lane >> 2);
        const int c0 = wn * 32 + (lane & 3) * 2;
#pragma unroll
        for (int mt = 0; mt < 4; mt++) {
            int rowA = r0 + mt * 16, rowB = rowA + 8;
#pragma unroll
            for (int nt = 0; nt < 4; nt++) {
                int col = c0 + nt * 8;
                if (col < 64) {
                    *(__half2*)&g_dtr_h[rowA * DTR + col] =
                        __floats2half2_rn(acc[mt][nt][0], acc[mt][nt][1]);
                    *(__half2*)&g_dtr_h[rowB * DTR + col] =
                        __floats2half2_rn(acc[mt][nt][2], acc[mt][nt][3]);
                } else if (col < 80) {
                    *(float2*)&g_Bm[rowA * DS + col - 64] =
                        make_float2(acc[mt][nt][0], acc[mt][nt][1]);
                    *(float2*)&g_Bm[rowB * DS + col - 64] =
                        make_float2(acc[mt][nt][2], acc[mt][nt][3]);
                } else if (col < 96) {
                    *(float2*)&g_Cm[rowA * DS + col - 80] =
                        make_float2(acc[mt][nt][0], acc[mt][nt][1]);
                    *(float2*)&g_Cm[rowB * DS + col - 80] =
                        make_float2(acc[mt][nt][2], acc[mt][nt][3]);
                }
            }
        }
    } else {
        // dt: bias + softplus, transpose-store to g_dtT[(b*DI+d)*L + t]
        const int b  = (by * 128) >> 10;
        const int t0 = (by * 128) & (L_SZ - 1);
        float* stage = (float*)gsm;          // [64][132] per pass
#pragma unroll
        for (int pass = 0; pass < 2; ++pass) {
            __syncthreads();
            if ((wn >> 1) == pass) {
                int clbase = (wn & 1) * 32 + (lane & 3) * 2;
#pragma unroll
                for (int mt = 0; mt < 4; mt++) {
                    int rA = wm * 64 + mt * 16 + (lane >> 2);
#pragma unroll
                    for (int nt = 0; nt < 4; nt++) {
                        int cl = clbase + nt * 8;
                        int dcol = bx * 128 + pass * 64 + cl;
                        float b0 = bias[dcol], b1 = bias[dcol + 1];
                        float v;
                        v = acc[mt][nt][0] + b0;
                        stage[cl * 132 + rA] = (v > 20.f) ? v : log1pf(__expf(v));
                        v = acc[mt][nt][1] + b1;
                        stage[(cl + 1) * 132 + rA] = (v > 20.f) ? v : log1pf(__expf(v));
                        v = acc[mt][nt][2] + b0;
                        stage[cl * 132 + rA + 8] = (v > 20.f) ? v : log1pf(__expf(v));
                        v = acc[mt][nt][3] + b1;
                        stage[(cl + 1) * 132 + rA + 8] = (v > 20.f) ? v : log1pf(__expf(v));
                    }
                }
            }
            __syncthreads();
            int dl = tid >> 2, tq = tid & 3;
            float* dst = &g_dtT[((size_t)b * DI + bx * 128 + pass * 64 + dl) * L_SZ
                                + t0 + tq * 32];
            const float* srcp = stage + dl * 132 + tq * 32;
#pragma unroll
            for (int i = 0; i < 8; i++)
                ((float4*)dst)[i] = ((const float4*)srcp)[i];
        }
    }
}

__global__ __launch_bounds__(256) void gemm_inproj_kernel() {
    gemm_core<0>(g_nh, g_wih, g_xz, 2 * DI, DM, nullptr, nullptr);
}
__global__ __launch_bounds__(256) void gemm_outproj_kernel(const float* __restrict__ x,
                                                           float* __restrict__ out) {
    gemm_core<1>(g_yh, g_woh, out, DM, DI, x, nullptr);
}
__global__ __launch_bounds__(256) void gemm_xproj_kernel() {
    gemm_core<2>(g_xch, g_xpwh, nullptr, 128, DI, nullptr, nullptr);
}
__global__ __launch_bounds__(256) void gemm_dt_kernel(const float* __restrict__ dtb) {
    gemm_core<3>(g_dtr_h, g_dtwh, nullptr, 128, DTR, nullptr, dtb);
}

// ---------------- conv + silu (writes xc fp32, xc fp16, xcT) ----------------
__global__ __launch_bounds__(256) void conv_silu_kernel(const float* __restrict__ convw,
                                                        const float* __restrict__ convb) {
    int c = blockIdx.x * 256 + threadIdx.x;
    int m0 = blockIdx.y * 8;
    int b = m0 >> 10, t0 = m0 & (L_SZ - 1);
    unsigned char mk[11];
#pragma unroll
    for (int r = 0; r < 11; r++) {
        int mrow = m0 - 3 + r;
        mk[r] = (mrow >= 0) ? g_maskc[mrow] : (unsigned char)0;
    }
    float w0 = convw[c * 4 + 0], w1 = convw[c * 4 + 1];
    float w2 = convw[c * 4 + 2], w3 = convw[c * 4 + 3];
    float cb = convb[c];
    float xr[11];
#pragma unroll
    for (int r = 0; r < 11; r++) {
        int mrow = m0 - 3 + r;
        xr[r] = (mrow >= 0) ? g_xz[(size_t)mrow * (2 * DI) + c] : 0.f;
    }
    float xcv[8];
#pragma unroll
    for (int tt = 0; tt < 8; tt++) {
        int tloc = t0 + tt;
        float acc = cb;
        if (mk[tt + 3]) {
            acc += w3 * xr[tt + 3];
            if (tloc >= 1 && mk[tt + 2]) {
                acc += w2 * xr[tt + 2];
                if (tloc >= 2 && mk[tt + 1]) {
                    acc += w1 * xr[tt + 1];
                    if (tloc >= 3 && mk[tt]) acc += w0 * xr[tt];
                }
            }
        }
        float s = acc / (1.0f + __expf(-acc));
        xcv[tt] = s;
        g_xc[(size_t)(m0 + tt) * DI + c] = s;
        g_xch[(size_t)(m0 + tt) * DI + c] = __float2half_rn(s);
    }
    float4* p = (float4*)&g_xcT[((size_t)b * DI + c) * L_SZ + t0];
    p[0] = make_float4(xcv[0], xcv[1], xcv[2], xcv[3]);
    p[1] = make_float4(xcv[4], xcv[5], xcv[6], xcv[7]);
}

// ---------------- selective scan --------------------------------------------
__global__ __launch_bounds__(256) void scan_kernel(const float* __restrict__ A_log) {
    int gid = (blockIdx.x * 256 + threadIdx.x) >> 4;
    int s = threadIdx.x & 15;
    int b = gid >> 11;
    int d = gid & (DI - 1);
    float a = -__expf(A_log[d * DS + s]);
    const float* dtp = g_dtT + (size_t)(b * DI + d) * L_SZ;
    const float* xcp = g_xcT + (size_t)(b * DI + d) * L_SZ;
    const float* Bp  = g_Bm + (size_t)b * L_SZ * DS;
    const float* Cp  = g_Cm + (size_t)b * L_SZ * DS;
    const unsigned char* mp = g_maskc + b * L_SZ;
    float* yp = g_yT + (size_t)(b * DI + d) * L_SZ;

    float h = 0.f, ybuf = 0.f;
    for (int t4 = 0; t4 < L_SZ; t4 += 4) {
        float4 dt4 = *(const float4*)(dtp + t4);
        float4 xc4 = *(const float4*)(xcp + t4);
        float dts[4] = {dt4.x, dt4.y, dt4.z, dt4.w};
        float xcs[4] = {xc4.x, xc4.y, xc4.z, xc4.w};
#pragma unroll
        for (int q = 0; q < 4; q++) {
            int t = t4 + q;
            float Bv = Bp[t * DS + s];
            float Cv = Cp[t * DS + s];
            float dA = __expf(dts[q] * a);
            float hn = fmaf(dA, h, dts[q] * Bv * xcs[q]);
            h = mp[t] ? hn : 0.f;
            float p = h * Cv;
            p += __shfl_xor_sync(0xffffffffu, p, 8);
            p += __shfl_xor_sync(0xffffffffu, p, 4);
            p += __shfl_xor_sync(0xffffffffu, p, 2);
            p += __shfl_xor_sync(0xffffffffu, p, 1);
            if ((t & 15) == s) ybuf = p;
            if ((t & 15) == 15) yp[(t & ~15) + s] = ybuf;
        }
    }
}

// ---------------- combine: (y + D*x_c)*silu(z) -> fp16 ----------------------
__global__ void combine_kernel(const float* __restrict__ Dp) {
    __shared__ float sh[32][33];
    int b = blockIdx.z, d0 = blockIdx.x * 32, t0 = blockIdx.y * 32;
    int tx = threadIdx.x, ty = threadIdx.y;
#pragma unroll
    for (int i = 0; i < 4; i++) {
        int d = d0 + ty + i * 8;
        sh[ty + i * 8][tx] = g_yT[((size_t)b * DI + d) * L_SZ + t0 + tx];
    }
    __syncthreads();
#pragma unroll
    for (int i = 0; i < 4; i++) {
        int t = t0 + ty + i * 8;
        size_t m = (size_t)b * L_SZ + t;
        int d = d0 + tx;
        float yv  = sh[tx][ty + i * 8];
        float xcv = g_xc[m * DI + d];
        float zv  = g_xz[m * (2 * DI) + DI + d];
        float yy  = fmaf(Dp[d], xcv, yv);
        float sz  = zv / (1.0f + __expf(-zv));
        g_yh[m * DI + d] = __float2half_rn(yy * sz);
    }
}

// ---------------- launch ----------------------------------------------------
extern "C" void kernel_launch(void* const* d_in, const int* in_sizes, int n_in,
                              void* d_out, int out_size) {
    const float* x        = (const float*)d_in[0];
    const void*  maskraw  = d_in[1];
    const float* rms_w    = (const float*)d_in[2];
    const float* in_proj  = (const float*)d_in[3];
    const float* conv_w   = (const float*)d_in[4];
    const float* conv_b   = (const float*)d_in[5];
    const float* x_proj   = (const float*)d_in[6];
    const float* dt_proj  = (const float*)d_in[7];
    const float* dt_b     = (const float*)d_in[8];
    const float* A_log    = (const float*)d_in[9];
    const float* Dvec     = (const float*)d_in[10];
    const float* out_proj = (const float*)d_in[11];
    float* out = (float*)d_out;

    cudaFuncSetAttribute(gemm_inproj_kernel,  cudaFuncAttributeMaxDynamicSharedMemorySize, G_SMEM);
    cudaFuncSetAttribute(gemm_outproj_kernel, cudaFuncAttributeMaxDynamicSharedMemorySize, G_SMEM);
    cudaFuncSetAttribute(gemm_xproj_kernel,   cudaFuncAttributeMaxDynamicSharedMemorySize, G_SMEM);
    cudaFuncSetAttribute(gemm_dt_kernel,      cudaFuncAttributeMaxDynamicSharedMemorySize, G_SMEM);

    // 1 rmsnorm, 2 cvt_win, 3 cvt_small, 4 gemm_in (profiled), 5 conv_silu,
    // 6 gemm_xproj, 7 gemm_dt, 8 scan, 9 combine, 10 cvt_wout, 11 gemm_out
    rmsnorm_kernel<<<NTOK, 256>>>(x, rms_w, maskraw);
    cvt_win_kernel<<<(2 * DI * DM / 4 + 255) / 256, 256>>>(in_proj);
    cvt_small_kernel<<<((128 * DI + DI * DTR) / 4 + 255) / 256, 256>>>(x_proj, dt_proj);

    dim3 g1((2 * DI) / 128, NTOK / 128);
    gemm_inproj_kernel<<<g1, 256, G_SMEM>>>();

    dim3 gc(DI / 256, NTOK / 8);
    conv_silu_kernel<<<gc, 256>>>(conv_w, conv_b);

    dim3 gx(1, NTOK / 128);
    gemm_xproj_kernel<<<gx, 256, G_SMEM>>>();

    dim3 gd(DI / 128, NTOK / 128);
    gemm_dt_kernel<<<gd, 256, G_SMEM>>>(dt_b);

    scan_kernel<<<(B_SZ * DI * DS) / 256, 256>>>(A_log);

    dim3 tg(DI / 32, L_SZ / 32, B_SZ);
    dim3 tb(32, 8);
    combine_kernel<<<tg, tb>>>(Dvec);

    cvt_wout_kernel<<<(DM * DI / 4 + 255) / 256, 256>>>(out_proj);

    dim3 g2(DM / 128, NTOK / 128);
    gemm_outproj_kernel<<<g2, 256, G_SMEM>>>(x, out);
}